// round 12
// baseline (speedup 1.0000x reference)
#include <cuda_runtime.h>
#include <stdint.h>

#define NN 100000
#define NE 1200000
#define SCAN_B 1024
#define NBLK ((NN + SCAN_B - 1) / SCAN_B)   // 98

// ---------------- scratch (device globals: allocation-free) ----------------
__device__ __align__(128) float g_hA[NN * 64];    // h ping
__device__ __align__(128) float g_hB[NN * 64];    // h pong
__device__ __align__(128) float g_dinv[NN];
__device__ __align__(128) int   g_cnt[NN];        // in-degree (excl. self)
__device__ __align__(128) int   g_rowptr[NN + 1];
__device__ __align__(128) int   g_wpos[NN];
__device__ __align__(128) int   g_src[NE];        // CSR: sources grouped by dst
__device__ __align__(128) int   g_tmp[NN];
__device__ __align__(128) int   g_bsum[NBLK];

// ---------------- per-block int64 probe (ei L2-cached => free) -------------
__device__ __forceinline__ int probe_is64(const int* ei) {
    int az = 1;
#pragma unroll
    for (int j = 0; j < 32; j++) az &= (ei[2 * j + 1] == 0);
    return az;
}

// ---------------- gather: full batches of 8 + predicated tail --------------
// Exactly `deg` loads issued (predicated-off loads emit no wavefronts), with
// batched MLP in both body and tail.
template <int GRP>
__device__ __forceinline__ void gather(const float4* __restrict__ h4,
                                       int e, int end, int g, float4& acc) {
    for (; e + 8 <= end; e += 8) {
        int s[8];
#pragma unroll
        for (int u = 0; u < 8; u++) s[u] = g_src[e + u];
        float4 v[8];
#pragma unroll
        for (int u = 0; u < 8; u++) v[u] = h4[s[u] * GRP + g];
#pragma unroll
        for (int u = 0; u < 8; u++) {
            acc.x += v[u].x; acc.y += v[u].y; acc.z += v[u].z; acc.w += v[u].w;
        }
    }
    int rem = end - e;                       // 0..7
    if (rem) {
        int s[8];
        float4 v[8];
#pragma unroll
        for (int u = 0; u < 8; u++)
            if (u < rem) { s[u] = g_src[e + u]; v[u] = h4[s[u] * GRP + g]; }
#pragma unroll
        for (int u = 0; u < 8; u++)
            if (u < rem) {
                acc.x += v[u].x; acc.y += v[u].y;
                acc.z += v[u].z; acc.w += v[u].w;
            }
    }
}

// ---------------- count in-degrees, 2 edges/thread (g_cnt pre-zeroed) ------
__global__ void k_edges(const int* __restrict__ ei) {
    __shared__ int s_is64;
    if (threadIdx.x == 0) s_is64 = probe_is64(ei);
    __syncthreads();
    int stride = s_is64 ? 2 : 1;
    int e0 = (blockIdx.x * blockDim.x + threadIdx.x) * 2;
    if (e0 < NE) {
        int c0 = ei[(size_t)(NE + e0) * stride];
        c0 = min(max(c0, 0), NN - 1);
        int c1 = -1;
        if (e0 + 1 < NE) {
            c1 = ei[(size_t)(NE + e0 + 1) * stride];
            c1 = min(max(c1, 0), NN - 1);
        }
        atomicAdd(&g_cnt[c0], 1);
        if (c1 >= 0) atomicAdd(&g_cnt[c1], 1);
    }
}

// ---------------- scan pass A: block-local inclusive scan ------------------
__global__ void k_scanA() {
    __shared__ int sm[SCAN_B];
    int i = blockIdx.x * SCAN_B + threadIdx.x;
    int v = (i < NN) ? g_cnt[i] : 0;
    sm[threadIdx.x] = v;
    __syncthreads();
    for (int off = 1; off < SCAN_B; off <<= 1) {
        int t = (threadIdx.x >= off) ? sm[threadIdx.x - off] : 0;
        __syncthreads();
        sm[threadIdx.x] += t;
        __syncthreads();
    }
    if (i < NN) g_tmp[i] = sm[threadIdx.x];
    if (threadIdx.x == SCAN_B - 1) g_bsum[blockIdx.x] = sm[threadIdx.x];
}

// ---------------- scan pass B: inline block-sum scan + finalize ------------
__global__ void k_scanC() {
    __shared__ int bs[128];
    if (threadIdx.x < 128)
        bs[threadIdx.x] = (threadIdx.x < NBLK) ? g_bsum[threadIdx.x] : 0;
    __syncthreads();
    for (int off = 1; off < 128; off <<= 1) {
        int t = (threadIdx.x >= off && threadIdx.x < 128) ? bs[threadIdx.x - off] : 0;
        __syncthreads();
        if (threadIdx.x < 128) bs[threadIdx.x] += t;
        __syncthreads();
    }
    int base = (blockIdx.x == 0) ? 0 : bs[blockIdx.x - 1];

    int i = blockIdx.x * SCAN_B + threadIdx.x;
    if (i < NN) {
        int inc = g_tmp[i] + base;
        g_rowptr[i + 1] = inc;
        g_wpos[i] = inc - g_cnt[i];
        g_dinv[i] = rsqrtf((float)(g_cnt[i] + 1));   // +1 self-loop
    }
    if (i == 0) g_rowptr[0] = 0;
}

// ---------------- fused: CSR fill (2 edges/thread) + layer-1 GEMM ----------
__global__ void k_fill_gemm1(const int* __restrict__ ei, int fill_blocks,
                             const float* __restrict__ x,
                             const float* __restrict__ W,
                             float* __restrict__ hout) {
    if (blockIdx.x < fill_blocks) {
        __shared__ int s_is64;
        if (threadIdx.x == 0) s_is64 = probe_is64(ei);
        __syncthreads();
        int stride = s_is64 ? 2 : 1;
        int e0 = (blockIdx.x * blockDim.x + threadIdx.x) * 2;
        if (e0 < NE) {
            int r0 = ei[(size_t)e0 * stride];
            int c0 = ei[(size_t)(NE + e0) * stride];
            r0 = min(max(r0, 0), NN - 1);
            c0 = min(max(c0, 0), NN - 1);
            int r1 = -1, c1 = -1;
            if (e0 + 1 < NE) {
                r1 = ei[(size_t)(e0 + 1) * stride];
                c1 = ei[(size_t)(NE + e0 + 1) * stride];
                r1 = min(max(r1, 0), NN - 1);
                c1 = min(max(c1, 0), NN - 1);
            }
            int p0 = atomicAdd(&g_wpos[c0], 1);
            int p1 = (c1 >= 0) ? atomicAdd(&g_wpos[c1], 1) : 0;
            g_src[p0] = r0;
            if (c1 >= 0) g_src[p1] = r1;
        }
        return;
    }

    // ---- gemm1: DIN=64, DN=32, 32 nodes/block ----
    __shared__ float Ws[64 * 32];                 // 8KB
    __shared__ float xsh[32 * 68];                // 32 rows, XST=68 (16B-aligned)
    __shared__ float dsh[32];

    for (int i = threadIdx.x; i < 64 * 32; i += blockDim.x) Ws[i] = W[i];

    const int n0 = (blockIdx.x - fill_blocks) * 32;
    const float4* __restrict__ xg = reinterpret_cast<const float4*>(x);
    for (int i = threadIdx.x; i < 512; i += blockDim.x) {      // 32 rows * 16 f4
        int row = i >> 4, fi = i & 15;
        reinterpret_cast<float4*>(xsh + row * 68)[fi] = xg[(size_t)(n0 + row) * 16 + fi];
    }
    if (threadIdx.x < 32) dsh[threadIdx.x] = g_dinv[n0 + threadIdx.x];
    __syncthreads();

    const int l = threadIdx.x & 31;               // node (local)
    const int w = threadIdx.x >> 5;               // col-quad (0..7)
    const float* xr = xsh + l * 68;
    const float4* W4 = reinterpret_cast<const float4*>(Ws);

    float a0 = 0.f, a1 = 0.f, a2 = 0.f, a3 = 0.f;
#pragma unroll
    for (int k4 = 0; k4 < 16; k4++) {
        float4 xk = reinterpret_cast<const float4*>(xr)[k4];
#pragma unroll
        for (int kk = 0; kk < 4; kk++) {
            float xv = (&xk.x)[kk];
            float4 wv = W4[(k4 * 4 + kk) * 8 + w];
            a0 = fmaf(xv, wv.x, a0);
            a1 = fmaf(xv, wv.y, a1);
            a2 = fmaf(xv, wv.z, a2);
            a3 = fmaf(xv, wv.w, a3);
        }
    }
    float dn = dsh[l];
    float4 o; o.x = dn * a0; o.y = dn * a1; o.z = dn * a2; o.w = dn * a3;
    reinterpret_cast<float4*>(hout)[(size_t)(n0 + l) * 8 + w] = o;
}

// ---------------- layer-1 agg + layer-2 GEMM (HD=32 -> DN=64) --------------
// Gather: 8 threads/node, 32 nodes/block. Compute: lane=node, warp=col-octet.
__global__ void k_agg_gemm2(const float* __restrict__ hin,
                            float* __restrict__ hout,
                            const float* __restrict__ bprev,
                            const float* __restrict__ W) {
    __shared__ float Ws[32 * 64];                 // 8KB
    __shared__ float xsh[32 * 36];                // 32 z-rows, XST=36
    __shared__ float dsh[32];

    for (int i = threadIdx.x; i < 32 * 64; i += blockDim.x) Ws[i] = W[i];

    const int t = blockIdx.x * blockDim.x + threadIdx.x;
    const int n = t >> 3;
    const int g = t & 7;
    const int nw = threadIdx.x >> 3;

    const float4* __restrict__ h4 = reinterpret_cast<const float4*>(hin);

    float4 acc = h4[n * 8 + g];                   // self term
    gather<8>(h4, g_rowptr[n], g_rowptr[n + 1], g, acc);

    const float dn = g_dinv[n];
    const float4 bp = reinterpret_cast<const float4*>(bprev)[g];
    float4 z;
    z.x = fmaxf(fmaf(dn, acc.x, bp.x), 0.0f);
    z.y = fmaxf(fmaf(dn, acc.y, bp.y), 0.0f);
    z.z = fmaxf(fmaf(dn, acc.z, bp.z), 0.0f);
    z.w = fmaxf(fmaf(dn, acc.w, bp.w), 0.0f);
    reinterpret_cast<float4*>(xsh + nw * 36)[g] = z;
    if (g == 0) dsh[nw] = dn;
    __syncthreads();

    // compute: node = lane, cols = warp*8 .. warp*8+7
    const int l = threadIdx.x & 31;
    const int w = threadIdx.x >> 5;
    const float* xr = xsh + l * 36;
    const float4* W4 = reinterpret_cast<const float4*>(Ws);

    float a[8];
#pragma unroll
    for (int j = 0; j < 8; j++) a[j] = 0.f;
#pragma unroll
    for (int k4 = 0; k4 < 8; k4++) {
        float4 xk = reinterpret_cast<const float4*>(xr)[k4];
#pragma unroll
        for (int kk = 0; kk < 4; kk++) {
            float xv = (&xk.x)[kk];
            int k = k4 * 4 + kk;
            float4 w0 = W4[k * 16 + w * 2];
            float4 w1 = W4[k * 16 + w * 2 + 1];
            a[0] = fmaf(xv, w0.x, a[0]); a[1] = fmaf(xv, w0.y, a[1]);
            a[2] = fmaf(xv, w0.z, a[2]); a[3] = fmaf(xv, w0.w, a[3]);
            a[4] = fmaf(xv, w1.x, a[4]); a[5] = fmaf(xv, w1.y, a[5]);
            a[6] = fmaf(xv, w1.z, a[6]); a[7] = fmaf(xv, w1.w, a[7]);
        }
    }
    const float dn2 = dsh[l];
    const int n2 = blockIdx.x * 32 + l;
    float4 o0, o1;
    o0.x = dn2 * a[0]; o0.y = dn2 * a[1]; o0.z = dn2 * a[2]; o0.w = dn2 * a[3];
    o1.x = dn2 * a[4]; o1.y = dn2 * a[5]; o1.z = dn2 * a[6]; o1.w = dn2 * a[7];
    reinterpret_cast<float4*>(hout)[(size_t)n2 * 16 + w * 2]     = o0;
    reinterpret_cast<float4*>(hout)[(size_t)n2 * 16 + w * 2 + 1] = o1;
}

// ---------------- layer-2 agg + layer-3 GEMM (HD=64 -> DN=64) --------------
// 512 threads, 32 nodes/block: halves W reload traffic vs 16 nodes/block.
// Gather: 16 threads/node. Compute: lane=node (32), warp=col-quad (16).
__global__ void k_agg_gemm3(const float* __restrict__ hin,
                            float* __restrict__ hout,
                            const float* __restrict__ bprev,
                            const float* __restrict__ W) {
    __shared__ float Ws[64 * 64];                 // 16KB
    __shared__ float xsh[32 * 68];                // 32 z-rows, XST=68
    __shared__ float dsh[32];

    for (int i = threadIdx.x; i < 64 * 64; i += blockDim.x) Ws[i] = W[i];

    const int t = blockIdx.x * blockDim.x + threadIdx.x;   // blockDim = 512
    const int n = t >> 4;
    const int g = t & 15;
    const int nw = threadIdx.x >> 4;              // 0..31

    const float4* __restrict__ h4 = reinterpret_cast<const float4*>(hin);

    float4 acc = h4[n * 16 + g];
    gather<16>(h4, g_rowptr[n], g_rowptr[n + 1], g, acc);

    const float dn = g_dinv[n];
    const float4 bp = reinterpret_cast<const float4*>(bprev)[g];
    float4 z;
    z.x = fmaxf(fmaf(dn, acc.x, bp.x), 0.0f);
    z.y = fmaxf(fmaf(dn, acc.y, bp.y), 0.0f);
    z.z = fmaxf(fmaf(dn, acc.z, bp.z), 0.0f);
    z.w = fmaxf(fmaf(dn, acc.w, bp.w), 0.0f);
    reinterpret_cast<float4*>(xsh + nw * 68)[g] = z;
    if (g == 0) dsh[nw] = dn;
    __syncthreads();

    // compute: node = tid&31, q = tid>>5 (0..15); warp-uniform W address
    const int l = threadIdx.x & 31;
    const int q = threadIdx.x >> 5;
    const float* xr = xsh + l * 68;
    const float4* W4 = reinterpret_cast<const float4*>(Ws);

    float a0 = 0.f, a1 = 0.f, a2 = 0.f, a3 = 0.f;
#pragma unroll
    for (int k4 = 0; k4 < 16; k4++) {
        float4 xk = reinterpret_cast<const float4*>(xr)[k4];
#pragma unroll
        for (int kk = 0; kk < 4; kk++) {
            float xv = (&xk.x)[kk];
            float4 wv = W4[(k4 * 4 + kk) * 16 + q];
            a0 = fmaf(xv, wv.x, a0);
            a1 = fmaf(xv, wv.y, a1);
            a2 = fmaf(xv, wv.z, a2);
            a3 = fmaf(xv, wv.w, a3);
        }
    }
    const float dn2 = dsh[l];
    const int n2 = blockIdx.x * 32 + l;
    float4 o; o.x = dn2 * a0; o.y = dn2 * a1; o.z = dn2 * a2; o.w = dn2 * a3;
    reinterpret_cast<float4*>(hout)[(size_t)n2 * 16 + q] = o;
}

// ---------------- fused aggregate + bias + row L2-normalize ----------------
__global__ void k_agg_final(const float* __restrict__ hin,
                            const float* __restrict__ b3,
                            float* __restrict__ out) {
    const int t = blockIdx.x * blockDim.x + threadIdx.x;
    const int n = t >> 4;          // GRP = 16
    const int g = t & 15;

    const float4* __restrict__ h4 = reinterpret_cast<const float4*>(hin);

    float4 acc = h4[n * 16 + g];
    gather<16>(h4, g_rowptr[n], g_rowptr[n + 1], g, acc);

    const float dn = g_dinv[n];
    const float4 bp = reinterpret_cast<const float4*>(b3)[g];
    float4 v;
    v.x = fmaf(dn, acc.x, bp.x);
    v.y = fmaf(dn, acc.y, bp.y);
    v.z = fmaf(dn, acc.z, bp.z);
    v.w = fmaf(dn, acc.w, bp.w);

    float s = v.x * v.x + v.y * v.y + v.z * v.z + v.w * v.w;
    s += __shfl_xor_sync(0xffffffffu, s, 1);
    s += __shfl_xor_sync(0xffffffffu, s, 2);
    s += __shfl_xor_sync(0xffffffffu, s, 4);
    s += __shfl_xor_sync(0xffffffffu, s, 8);
    float inv = 1.0f / fmaxf(sqrtf(s), 1e-12f);

    float4 o;
    o.x = v.x * inv; o.y = v.y * inv; o.z = v.z * inv; o.w = v.w * inv;
    reinterpret_cast<float4*>(out)[n * 16 + g] = o;
}

// ---------------- launch ----------------
extern "C" void kernel_launch(void* const* d_in, const int* in_sizes, int n_in,
                              void* d_out, int out_size) {
    const float* x  = (const float*)d_in[0];
    const int*   ei = (const int*)d_in[1];   // int32 (JAX x64 off) or int64 via probe
    const float* W1 = (const float*)d_in[2];
    const float* b1 = (const float*)d_in[3];
    const float* W2 = (const float*)d_in[4];
    const float* b2 = (const float*)d_in[5];
    const float* W3 = (const float*)d_in[6];
    const float* b3 = (const float*)d_in[7];
    float* out = (float*)d_out;

    float *hA, *hB;
    cudaGetSymbolAddress((void**)&hA, g_hA);
    cudaGetSymbolAddress((void**)&hB, g_hB);
    int* cnt;
    cudaGetSymbolAddress((void**)&cnt, g_cnt);

    const int TB = 256;
    const int EDGE2_BLKS = (NE / 2 + TB - 1) / TB;   // 2344 (2 edges/thread)
    const int G1_BLKS    = NN / 32;                  // 3125 (32 nodes/block)

    // CSR + dinv (shared by all 3 layers)
    cudaMemsetAsync(cnt, 0, NN * sizeof(int));
    k_edges<<<EDGE2_BLKS, TB>>>(ei);
    k_scanA<<<NBLK, SCAN_B>>>();
    k_scanC<<<NBLK, SCAN_B>>>();

    // CSR fill + Layer-1 GEMM (independent, one kernel)
    k_fill_gemm1<<<EDGE2_BLKS + G1_BLKS, TB>>>(ei, EDGE2_BLKS, x, W1, hA);

    // Layer 1 aggregate + Layer 2 GEMM: hB = dinv * (relu(agg(hA)+b1) @ W2)
    k_agg_gemm2<<<NN / 32, TB>>>(hA, hB, b1, W2);    // 3125 blocks, 256 thr
    // Layer 2 aggregate + Layer 3 GEMM: hA = dinv * (relu(agg(hB)+b2) @ W3)
    k_agg_gemm3<<<NN / 32, 512>>>(hB, hA, b2, W3);   // 3125 blocks, 512 thr
    // Layer 3 aggregate + b3 + row L2-normalize -> out
    k_agg_final<<<NN * 16 / TB, TB>>>(hA, b3, out);  // 6250 blocks
}

// round 14
// speedup vs baseline: 1.0989x; 1.0989x over previous
#include <cuda_runtime.h>
#include <cuda_fp16.h>
#include <stdint.h>

#define NN 100000
#define NE 1200000
#define SCAN_B 1024
#define NBLK ((NN + SCAN_B - 1) / SCAN_B)   // 98

// ---------------- scratch (device globals: allocation-free) ----------------
// h buffers stored fp16: halves gather traffic + wavefronts. Accum is fp32.
__device__ __align__(128) __half g_hA[NN * 64];   // h ping
__device__ __align__(128) __half g_hB[NN * 64];   // h pong
__device__ __align__(128) float  g_dinv[NN];
__device__ __align__(128) int    g_cnt[NN];       // in-degree (excl. self)
__device__ __align__(128) int    g_rowptr[NN + 1];
__device__ __align__(128) int    g_wpos[NN];
__device__ __align__(128) int    g_src[NE];       // CSR: sources grouped by dst
__device__ __align__(128) int    g_tmp[NN];
__device__ __align__(128) int    g_bsum[NBLK];

// ---------------- fp16 <-> fp32 helpers ----------------
__device__ __forceinline__ void acc_h4(uint2 p, float4& acc) {
    __half2 lo = *reinterpret_cast<__half2*>(&p.x);
    __half2 hi = *reinterpret_cast<__half2*>(&p.y);
    float2 a = __half22float2(lo);
    float2 b = __half22float2(hi);
    acc.x += a.x; acc.y += a.y; acc.z += b.x; acc.w += b.y;
}
__device__ __forceinline__ float4 h4_to_f4(uint2 p) {
    float4 r = {0.f, 0.f, 0.f, 0.f};
    acc_h4(p, r);
    return r;
}
__device__ __forceinline__ uint2 f4_to_h4(float4 v) {
    __half2 lo = __floats2half2_rn(v.x, v.y);
    __half2 hi = __floats2half2_rn(v.z, v.w);
    uint2 r;
    r.x = *reinterpret_cast<uint32_t*>(&lo);
    r.y = *reinterpret_cast<uint32_t*>(&hi);
    return r;
}

// ---------------- per-block int64 probe (ei L2-cached => free) -------------
__device__ __forceinline__ int probe_is64(const int* ei) {
    int az = 1;
#pragma unroll
    for (int j = 0; j < 32; j++) az &= (ei[2 * j + 1] == 0);
    return az;
}

// ---------------- gather: unrolled-8 body + scalar tail (round-10 shape) ---
// GRP = row stride in uint2 units = HD/4 (same arithmetic as fp32 version).
template <int GRP>
__device__ __forceinline__ void gather(const uint2* __restrict__ h2,
                                       int e, int end, int g, float4& acc) {
    for (; e + 8 <= end; e += 8) {
        int s[8];
#pragma unroll
        for (int u = 0; u < 8; u++) s[u] = g_src[e + u];
        uint2 v[8];
#pragma unroll
        for (int u = 0; u < 8; u++) v[u] = h2[s[u] * GRP + g];
#pragma unroll
        for (int u = 0; u < 8; u++) acc_h4(v[u], acc);
    }
    for (; e < end; e++) acc_h4(h2[g_src[e] * GRP + g], acc);
}

// ---------------- count in-degrees, 2 edges/thread (g_cnt pre-zeroed) ------
__global__ void k_edges(const int* __restrict__ ei) {
    __shared__ int s_is64;
    if (threadIdx.x == 0) s_is64 = probe_is64(ei);
    __syncthreads();
    int stride = s_is64 ? 2 : 1;
    int e0 = (blockIdx.x * blockDim.x + threadIdx.x) * 2;
    if (e0 < NE) {
        int c0 = ei[(size_t)(NE + e0) * stride];
        c0 = min(max(c0, 0), NN - 1);
        int c1 = -1;
        if (e0 + 1 < NE) {
            c1 = ei[(size_t)(NE + e0 + 1) * stride];
            c1 = min(max(c1, 0), NN - 1);
        }
        atomicAdd(&g_cnt[c0], 1);
        if (c1 >= 0) atomicAdd(&g_cnt[c1], 1);
    }
}

// ---------------- scan pass A: block-local inclusive scan ------------------
__global__ void k_scanA() {
    __shared__ int sm[SCAN_B];
    int i = blockIdx.x * SCAN_B + threadIdx.x;
    int v = (i < NN) ? g_cnt[i] : 0;
    sm[threadIdx.x] = v;
    __syncthreads();
    for (int off = 1; off < SCAN_B; off <<= 1) {
        int t = (threadIdx.x >= off) ? sm[threadIdx.x - off] : 0;
        __syncthreads();
        sm[threadIdx.x] += t;
        __syncthreads();
    }
    if (i < NN) g_tmp[i] = sm[threadIdx.x];
    if (threadIdx.x == SCAN_B - 1) g_bsum[blockIdx.x] = sm[threadIdx.x];
}

// ---------------- scan pass B: inline block-sum scan + finalize ------------
__global__ void k_scanC() {
    __shared__ int bs[128];
    if (threadIdx.x < 128)
        bs[threadIdx.x] = (threadIdx.x < NBLK) ? g_bsum[threadIdx.x] : 0;
    __syncthreads();
    for (int off = 1; off < 128; off <<= 1) {
        int t = (threadIdx.x >= off && threadIdx.x < 128) ? bs[threadIdx.x - off] : 0;
        __syncthreads();
        if (threadIdx.x < 128) bs[threadIdx.x] += t;
        __syncthreads();
    }
    int base = (blockIdx.x == 0) ? 0 : bs[blockIdx.x - 1];

    int i = blockIdx.x * SCAN_B + threadIdx.x;
    if (i < NN) {
        int inc = g_tmp[i] + base;
        g_rowptr[i + 1] = inc;
        g_wpos[i] = inc - g_cnt[i];
        g_dinv[i] = rsqrtf((float)(g_cnt[i] + 1));   // +1 self-loop
    }
    if (i == 0) g_rowptr[0] = 0;
}

// ---------------- fused: CSR fill (2 edges/thread) + layer-1 GEMM ----------
__global__ void k_fill_gemm1(const int* __restrict__ ei, int fill_blocks,
                             const float* __restrict__ x,
                             const float* __restrict__ W,
                             __half* __restrict__ hout) {
    if (blockIdx.x < fill_blocks) {
        __shared__ int s_is64;
        if (threadIdx.x == 0) s_is64 = probe_is64(ei);
        __syncthreads();
        int stride = s_is64 ? 2 : 1;
        int e0 = (blockIdx.x * blockDim.x + threadIdx.x) * 2;
        if (e0 < NE) {
            int r0 = ei[(size_t)e0 * stride];
            int c0 = ei[(size_t)(NE + e0) * stride];
            r0 = min(max(r0, 0), NN - 1);
            c0 = min(max(c0, 0), NN - 1);
            int r1 = -1, c1 = -1;
            if (e0 + 1 < NE) {
                r1 = ei[(size_t)(e0 + 1) * stride];
                c1 = ei[(size_t)(NE + e0 + 1) * stride];
                r1 = min(max(r1, 0), NN - 1);
                c1 = min(max(c1, 0), NN - 1);
            }
            int p0 = atomicAdd(&g_wpos[c0], 1);
            int p1 = (c1 >= 0) ? atomicAdd(&g_wpos[c1], 1) : 0;
            g_src[p0] = r0;
            if (c1 >= 0) g_src[p1] = r1;
        }
        return;
    }

    // ---- gemm1: DIN=64, DN=32, 32 nodes/block ----
    __shared__ float Ws[64 * 32];                 // 8KB
    __shared__ float xsh[32 * 68];                // 32 rows, XST=68 (16B-aligned)
    __shared__ float dsh[32];

    for (int i = threadIdx.x; i < 64 * 32; i += blockDim.x) Ws[i] = W[i];

    const int n0 = (blockIdx.x - fill_blocks) * 32;
    const float4* __restrict__ xg = reinterpret_cast<const float4*>(x);
    for (int i = threadIdx.x; i < 512; i += blockDim.x) {      // 32 rows * 16 f4
        int row = i >> 4, fi = i & 15;
        reinterpret_cast<float4*>(xsh + row * 68)[fi] = xg[(size_t)(n0 + row) * 16 + fi];
    }
    if (threadIdx.x < 32) dsh[threadIdx.x] = g_dinv[n0 + threadIdx.x];
    __syncthreads();

    const int l = threadIdx.x & 31;               // node (local)
    const int w = threadIdx.x >> 5;               // col-quad (0..7)
    const float* xr = xsh + l * 68;
    const float4* W4 = reinterpret_cast<const float4*>(Ws);

    float a0 = 0.f, a1 = 0.f, a2 = 0.f, a3 = 0.f;
#pragma unroll
    for (int k4 = 0; k4 < 16; k4++) {
        float4 xk = reinterpret_cast<const float4*>(xr)[k4];
#pragma unroll
        for (int kk = 0; kk < 4; kk++) {
            float xv = (&xk.x)[kk];
            float4 wv = W4[(k4 * 4 + kk) * 8 + w];
            a0 = fmaf(xv, wv.x, a0);
            a1 = fmaf(xv, wv.y, a1);
            a2 = fmaf(xv, wv.z, a2);
            a3 = fmaf(xv, wv.w, a3);
        }
    }
    float dn = dsh[l];
    float4 o; o.x = dn * a0; o.y = dn * a1; o.z = dn * a2; o.w = dn * a3;
    // row = 32 halves = 8 uint2; thread w owns cols w*4..w*4+3 = uint2 index w
    reinterpret_cast<uint2*>(hout)[(size_t)(n0 + l) * 8 + w] = f4_to_h4(o);
}

// ---------------- layer-1 agg + layer-2 GEMM (HD=32 -> DN=64) --------------
// Gather: 8 threads/node, 32 nodes/block. Compute: lane=node, warp=col-octet.
__global__ void k_agg_gemm2(const __half* __restrict__ hin,
                            __half* __restrict__ hout,
                            const float* __restrict__ bprev,
                            const float* __restrict__ W) {
    __shared__ float Ws[32 * 64];                 // 8KB
    __shared__ float xsh[32 * 36];                // 32 z-rows, XST=36
    __shared__ float dsh[32];

    for (int i = threadIdx.x; i < 32 * 64; i += blockDim.x) Ws[i] = W[i];

    const int t = blockIdx.x * blockDim.x + threadIdx.x;
    const int n = t >> 3;
    const int g = t & 7;
    const int nw = threadIdx.x >> 3;

    const uint2* __restrict__ h2 = reinterpret_cast<const uint2*>(hin);

    float4 acc = h4_to_f4(h2[n * 8 + g]);         // self term
    gather<8>(h2, g_rowptr[n], g_rowptr[n + 1], g, acc);

    const float dn = g_dinv[n];
    const float4 bp = reinterpret_cast<const float4*>(bprev)[g];
    float4 z;
    z.x = fmaxf(fmaf(dn, acc.x, bp.x), 0.0f);
    z.y = fmaxf(fmaf(dn, acc.y, bp.y), 0.0f);
    z.z = fmaxf(fmaf(dn, acc.z, bp.z), 0.0f);
    z.w = fmaxf(fmaf(dn, acc.w, bp.w), 0.0f);
    reinterpret_cast<float4*>(xsh + nw * 36)[g] = z;
    if (g == 0) dsh[nw] = dn;
    __syncthreads();

    // compute: node = lane, cols = warp*8 .. warp*8+7
    const int l = threadIdx.x & 31;
    const int w = threadIdx.x >> 5;
    const float* xr = xsh + l * 36;
    const float4* W4 = reinterpret_cast<const float4*>(Ws);

    float a[8];
#pragma unroll
    for (int j = 0; j < 8; j++) a[j] = 0.f;
#pragma unroll
    for (int k4 = 0; k4 < 8; k4++) {
        float4 xk = reinterpret_cast<const float4*>(xr)[k4];
#pragma unroll
        for (int kk = 0; kk < 4; kk++) {
            float xv = (&xk.x)[kk];
            int k = k4 * 4 + kk;
            float4 w0 = W4[k * 16 + w * 2];
            float4 w1 = W4[k * 16 + w * 2 + 1];
            a[0] = fmaf(xv, w0.x, a[0]); a[1] = fmaf(xv, w0.y, a[1]);
            a[2] = fmaf(xv, w0.z, a[2]); a[3] = fmaf(xv, w0.w, a[3]);
            a[4] = fmaf(xv, w1.x, a[4]); a[5] = fmaf(xv, w1.y, a[5]);
            a[6] = fmaf(xv, w1.z, a[6]); a[7] = fmaf(xv, w1.w, a[7]);
        }
    }
    const float dn2 = dsh[l];
    const int n2 = blockIdx.x * 32 + l;
    float4 o0, o1;
    o0.x = dn2 * a[0]; o0.y = dn2 * a[1]; o0.z = dn2 * a[2]; o0.w = dn2 * a[3];
    o1.x = dn2 * a[4]; o1.y = dn2 * a[5]; o1.z = dn2 * a[6]; o1.w = dn2 * a[7];
    // row = 64 halves = 16 uint2; thread w owns cols w*8..w*8+7 = uint2 w*2, w*2+1
    reinterpret_cast<uint2*>(hout)[(size_t)n2 * 16 + w * 2]     = f4_to_h4(o0);
    reinterpret_cast<uint2*>(hout)[(size_t)n2 * 16 + w * 2 + 1] = f4_to_h4(o1);
}

// ---------------- layer-2 agg + layer-3 GEMM (HD=64 -> DN=64) --------------
// Gather: 16 threads/node, 16 nodes/block. Compute: half-lane=node, q=col-quad.
__global__ void k_agg_gemm3(const __half* __restrict__ hin,
                            __half* __restrict__ hout,
                            const float* __restrict__ bprev,
                            const float* __restrict__ W) {
    __shared__ float Ws[64 * 64];                 // 16KB
    __shared__ float xsh[16 * 68];                // 16 z-rows, XST=68
    __shared__ float dsh[16];

    for (int i = threadIdx.x; i < 64 * 64; i += blockDim.x) Ws[i] = W[i];

    const int t = blockIdx.x * blockDim.x + threadIdx.x;
    const int n = t >> 4;
    const int g = t & 15;
    const int nw = threadIdx.x >> 4;

    const uint2* __restrict__ h2 = reinterpret_cast<const uint2*>(hin);

    float4 acc = h4_to_f4(h2[n * 16 + g]);
    gather<16>(h2, g_rowptr[n], g_rowptr[n + 1], g, acc);

    const float dn = g_dinv[n];
    const float4 bp = reinterpret_cast<const float4*>(bprev)[g];
    float4 z;
    z.x = fmaxf(fmaf(dn, acc.x, bp.x), 0.0f);
    z.y = fmaxf(fmaf(dn, acc.y, bp.y), 0.0f);
    z.z = fmaxf(fmaf(dn, acc.z, bp.z), 0.0f);
    z.w = fmaxf(fmaf(dn, acc.w, bp.w), 0.0f);
    reinterpret_cast<float4*>(xsh + nw * 68)[g] = z;
    if (g == 0) dsh[nw] = dn;
    __syncthreads();

    // compute: nl = lane&15, q = warp*2 + (lane>>4)
    const int l  = threadIdx.x & 31;
    const int w  = threadIdx.x >> 5;
    const int nl = l & 15;
    const int q  = w * 2 + (l >> 4);
    const float* xr = xsh + nl * 68;
    const float4* W4 = reinterpret_cast<const float4*>(Ws);

    float a0 = 0.f, a1 = 0.f, a2 = 0.f, a3 = 0.f;
#pragma unroll
    for (int k4 = 0; k4 < 16; k4++) {
        float4 xk = reinterpret_cast<const float4*>(xr)[k4];
#pragma unroll
        for (int kk = 0; kk < 4; kk++) {
            float xv = (&xk.x)[kk];
            float4 wv = W4[(k4 * 4 + kk) * 16 + q];
            a0 = fmaf(xv, wv.x, a0);
            a1 = fmaf(xv, wv.y, a1);
            a2 = fmaf(xv, wv.z, a2);
            a3 = fmaf(xv, wv.w, a3);
        }
    }
    const float dn2 = dsh[nl];
    const int n2 = blockIdx.x * 16 + nl;
    float4 o; o.x = dn2 * a0; o.y = dn2 * a1; o.z = dn2 * a2; o.w = dn2 * a3;
    // row = 64 halves = 16 uint2; thread q owns cols q*4..q*4+3 = uint2 index q
    reinterpret_cast<uint2*>(hout)[(size_t)n2 * 16 + q] = f4_to_h4(o);
}

// ---------------- fused aggregate + bias + row L2-normalize (fp32 out) -----
__global__ void k_agg_final(const __half* __restrict__ hin,
                            const float* __restrict__ b3,
                            float* __restrict__ out) {
    const int t = blockIdx.x * blockDim.x + threadIdx.x;
    const int n = t >> 4;          // GRP = 16
    const int g = t & 15;

    const uint2* __restrict__ h2 = reinterpret_cast<const uint2*>(hin);

    float4 acc = h4_to_f4(h2[n * 16 + g]);
    gather<16>(h2, g_rowptr[n], g_rowptr[n + 1], g, acc);

    const float dn = g_dinv[n];
    const float4 bp = reinterpret_cast<const float4*>(b3)[g];
    float4 v;
    v.x = fmaf(dn, acc.x, bp.x);
    v.y = fmaf(dn, acc.y, bp.y);
    v.z = fmaf(dn, acc.z, bp.z);
    v.w = fmaf(dn, acc.w, bp.w);

    float s = v.x * v.x + v.y * v.y + v.z * v.z + v.w * v.w;
    s += __shfl_xor_sync(0xffffffffu, s, 1);
    s += __shfl_xor_sync(0xffffffffu, s, 2);
    s += __shfl_xor_sync(0xffffffffu, s, 4);
    s += __shfl_xor_sync(0xffffffffu, s, 8);
    float inv = 1.0f / fmaxf(sqrtf(s), 1e-12f);

    float4 o;
    o.x = v.x * inv; o.y = v.y * inv; o.z = v.z * inv; o.w = v.w * inv;
    reinterpret_cast<float4*>(out)[n * 16 + g] = o;
}

// ---------------- launch ----------------
extern "C" void kernel_launch(void* const* d_in, const int* in_sizes, int n_in,
                              void* d_out, int out_size) {
    const float* x  = (const float*)d_in[0];
    const int*   ei = (const int*)d_in[1];   // int32 (JAX x64 off) or int64 via probe
    const float* W1 = (const float*)d_in[2];
    const float* b1 = (const float*)d_in[3];
    const float* W2 = (const float*)d_in[4];
    const float* b2 = (const float*)d_in[5];
    const float* W3 = (const float*)d_in[6];
    const float* b3 = (const float*)d_in[7];
    float* out = (float*)d_out;

    __half *hA, *hB;
    cudaGetSymbolAddress((void**)&hA, g_hA);
    cudaGetSymbolAddress((void**)&hB, g_hB);
    int* cnt;
    cudaGetSymbolAddress((void**)&cnt, g_cnt);

    const int TB = 256;
    const int EDGE2_BLKS = (NE / 2 + TB - 1) / TB;   // 2344 (2 edges/thread)
    const int G1_BLKS    = NN / 32;                  // 3125 (32 nodes/block)

    // CSR + dinv (shared by all 3 layers)
    cudaMemsetAsync(cnt, 0, NN * sizeof(int));
    k_edges<<<EDGE2_BLKS, TB>>>(ei);
    k_scanA<<<NBLK, SCAN_B>>>();
    k_scanC<<<NBLK, SCAN_B>>>();

    // CSR fill + Layer-1 GEMM (independent, one kernel)
    k_fill_gemm1<<<EDGE2_BLKS + G1_BLKS, TB>>>(ei, EDGE2_BLKS, x, W1, hA);

    // Layer 1 aggregate + Layer 2 GEMM: hB = dinv * (relu(agg(hA)+b1) @ W2)
    k_agg_gemm2<<<NN / 32, TB>>>(hA, hB, b1, W2);    // 3125 blocks
    // Layer 2 aggregate + Layer 3 GEMM: hA = dinv * (relu(agg(hB)+b2) @ W3)
    k_agg_gemm3<<<NN / 16, TB>>>(hB, hA, b2, W3);    // 6250 blocks
    // Layer 3 aggregate + b3 + row L2-normalize -> out
    k_agg_final<<<NN * 16 / TB, TB>>>(hA, b3, out);  // 6250 blocks
}

// round 15
// speedup vs baseline: 1.2176x; 1.1081x over previous
#include <cuda_runtime.h>
#include <cuda_fp16.h>
#include <stdint.h>

#define NN 100000
#define NE 1200000
#define SCAN_B 1024
#define NBLK ((NN + SCAN_B - 1) / SCAN_B)   // 98

// ---------------- scratch (device globals: allocation-free) ----------------
// h buffers stored fp16: halves gather traffic + wavefronts. Accum is fp32.
__device__ __align__(128) __half g_hA[NN * 64];   // h ping
__device__ __align__(128) __half g_hB[NN * 64];   // h pong
__device__ __align__(128) float  g_dinv[NN];
__device__ __align__(128) int    g_cnt[NN];       // in-degree (excl. self)
__device__ __align__(128) int    g_rowptr[NN + 1];
__device__ __align__(128) int    g_wpos[NN];
__device__ __align__(128) int    g_src[NE];       // CSR: sources grouped by dst
__device__ __align__(128) int    g_tmp[NN];
__device__ __align__(128) int    g_bsum[NBLK];

// ---------------- fp16 <-> fp32 helpers (8-wide) ----------------
__device__ __forceinline__ void acc_h8(uint4 p, float4& A, float4& B) {
    __half2 h0 = *reinterpret_cast<__half2*>(&p.x);
    __half2 h1 = *reinterpret_cast<__half2*>(&p.y);
    __half2 h2 = *reinterpret_cast<__half2*>(&p.z);
    __half2 h3 = *reinterpret_cast<__half2*>(&p.w);
    float2 f0 = __half22float2(h0);
    float2 f1 = __half22float2(h1);
    float2 f2 = __half22float2(h2);
    float2 f3 = __half22float2(h3);
    A.x += f0.x; A.y += f0.y; A.z += f1.x; A.w += f1.y;
    B.x += f2.x; B.y += f2.y; B.z += f3.x; B.w += f3.y;
}
__device__ __forceinline__ uint4 f8_to_h8(float4 a, float4 b) {
    __half2 h0 = __floats2half2_rn(a.x, a.y);
    __half2 h1 = __floats2half2_rn(a.z, a.w);
    __half2 h2 = __floats2half2_rn(b.x, b.y);
    __half2 h3 = __floats2half2_rn(b.z, b.w);
    uint4 r;
    r.x = *reinterpret_cast<uint32_t*>(&h0);
    r.y = *reinterpret_cast<uint32_t*>(&h1);
    r.z = *reinterpret_cast<uint32_t*>(&h2);
    r.w = *reinterpret_cast<uint32_t*>(&h3);
    return r;
}
__device__ __forceinline__ uint2 f4_to_h4(float4 v) {
    __half2 lo = __floats2half2_rn(v.x, v.y);
    __half2 hi = __floats2half2_rn(v.z, v.w);
    uint2 r;
    r.x = *reinterpret_cast<uint32_t*>(&lo);
    r.y = *reinterpret_cast<uint32_t*>(&hi);
    return r;
}

// ---------------- per-block int64 probe (ei L2-cached => free) -------------
__device__ __forceinline__ int probe_is64(const int* ei) {
    int az = 1;
#pragma unroll
    for (int j = 0; j < 32; j++) az &= (ei[2 * j + 1] == 0);
    return az;
}

// ---------------- gather: uint4 (8 halves) per edge, unroll-4 + tail -------
// GRPU4 = row stride in uint4 units (HD/8). Halves LDG count vs 8B loads.
template <int GRPU4>
__device__ __forceinline__ void gather16(const uint4* __restrict__ h,
                                         int e, int end, int g,
                                         float4& A, float4& B) {
    for (; e + 4 <= end; e += 4) {
        int s[4];
#pragma unroll
        for (int u = 0; u < 4; u++) s[u] = g_src[e + u];
        uint4 v[4];
#pragma unroll
        for (int u = 0; u < 4; u++) v[u] = h[(size_t)s[u] * GRPU4 + g];
#pragma unroll
        for (int u = 0; u < 4; u++) acc_h8(v[u], A, B);
    }
    for (; e < end; e++) acc_h8(h[(size_t)g_src[e] * GRPU4 + g], A, B);
}

// ---------------- count in-degrees, 2 edges/thread (g_cnt pre-zeroed) ------
__global__ void k_edges(const int* __restrict__ ei) {
    __shared__ int s_is64;
    if (threadIdx.x == 0) s_is64 = probe_is64(ei);
    __syncthreads();
    int stride = s_is64 ? 2 : 1;
    int e0 = (blockIdx.x * blockDim.x + threadIdx.x) * 2;
    if (e0 < NE) {
        int c0 = ei[(size_t)(NE + e0) * stride];
        c0 = min(max(c0, 0), NN - 1);
        int c1 = -1;
        if (e0 + 1 < NE) {
            c1 = ei[(size_t)(NE + e0 + 1) * stride];
            c1 = min(max(c1, 0), NN - 1);
        }
        atomicAdd(&g_cnt[c0], 1);
        if (c1 >= 0) atomicAdd(&g_cnt[c1], 1);
    }
}

// ---------------- scan pass A: block-local inclusive scan ------------------
__global__ void k_scanA() {
    __shared__ int sm[SCAN_B];
    int i = blockIdx.x * SCAN_B + threadIdx.x;
    int v = (i < NN) ? g_cnt[i] : 0;
    sm[threadIdx.x] = v;
    __syncthreads();
    for (int off = 1; off < SCAN_B; off <<= 1) {
        int t = (threadIdx.x >= off) ? sm[threadIdx.x - off] : 0;
        __syncthreads();
        sm[threadIdx.x] += t;
        __syncthreads();
    }
    if (i < NN) g_tmp[i] = sm[threadIdx.x];
    if (threadIdx.x == SCAN_B - 1) g_bsum[blockIdx.x] = sm[threadIdx.x];
}

// ---------------- scan pass B: inline block-sum scan + finalize ------------
__global__ void k_scanC() {
    __shared__ int bs[128];
    if (threadIdx.x < 128)
        bs[threadIdx.x] = (threadIdx.x < NBLK) ? g_bsum[threadIdx.x] : 0;
    __syncthreads();
    for (int off = 1; off < 128; off <<= 1) {
        int t = (threadIdx.x >= off && threadIdx.x < 128) ? bs[threadIdx.x - off] : 0;
        __syncthreads();
        if (threadIdx.x < 128) bs[threadIdx.x] += t;
        __syncthreads();
    }
    int base = (blockIdx.x == 0) ? 0 : bs[blockIdx.x - 1];

    int i = blockIdx.x * SCAN_B + threadIdx.x;
    if (i < NN) {
        int inc = g_tmp[i] + base;
        g_rowptr[i + 1] = inc;
        g_wpos[i] = inc - g_cnt[i];
        g_dinv[i] = rsqrtf((float)(g_cnt[i] + 1));   // +1 self-loop
    }
    if (i == 0) g_rowptr[0] = 0;
}

// ---------------- fused: CSR fill (2 edges/thread) + layer-1 GEMM ----------
__global__ void k_fill_gemm1(const int* __restrict__ ei, int fill_blocks,
                             const float* __restrict__ x,
                             const float* __restrict__ W,
                             __half* __restrict__ hout) {
    if (blockIdx.x < fill_blocks) {
        __shared__ int s_is64;
        if (threadIdx.x == 0) s_is64 = probe_is64(ei);
        __syncthreads();
        int stride = s_is64 ? 2 : 1;
        int e0 = (blockIdx.x * blockDim.x + threadIdx.x) * 2;
        if (e0 < NE) {
            int r0 = ei[(size_t)e0 * stride];
            int c0 = ei[(size_t)(NE + e0) * stride];
            r0 = min(max(r0, 0), NN - 1);
            c0 = min(max(c0, 0), NN - 1);
            int r1 = -1, c1 = -1;
            if (e0 + 1 < NE) {
                r1 = ei[(size_t)(e0 + 1) * stride];
                c1 = ei[(size_t)(NE + e0 + 1) * stride];
                r1 = min(max(r1, 0), NN - 1);
                c1 = min(max(c1, 0), NN - 1);
            }
            int p0 = atomicAdd(&g_wpos[c0], 1);
            int p1 = (c1 >= 0) ? atomicAdd(&g_wpos[c1], 1) : 0;
            g_src[p0] = r0;
            if (c1 >= 0) g_src[p1] = r1;
        }
        return;
    }

    // ---- gemm1: DIN=64, DN=32, 32 nodes/block ----
    __shared__ float Ws[64 * 32];                 // 8KB
    __shared__ float xsh[32 * 68];                // 32 rows, XST=68 (16B-aligned)
    __shared__ float dsh[32];

    for (int i = threadIdx.x; i < 64 * 32; i += blockDim.x) Ws[i] = W[i];

    const int n0 = (blockIdx.x - fill_blocks) * 32;
    const float4* __restrict__ xg = reinterpret_cast<const float4*>(x);
    for (int i = threadIdx.x; i < 512; i += blockDim.x) {      // 32 rows * 16 f4
        int row = i >> 4, fi = i & 15;
        reinterpret_cast<float4*>(xsh + row * 68)[fi] = xg[(size_t)(n0 + row) * 16 + fi];
    }
    if (threadIdx.x < 32) dsh[threadIdx.x] = g_dinv[n0 + threadIdx.x];
    __syncthreads();

    const int l = threadIdx.x & 31;               // node (local)
    const int w = threadIdx.x >> 5;               // col-quad (0..7)
    const float* xr = xsh + l * 68;
    const float4* W4 = reinterpret_cast<const float4*>(Ws);

    float a0 = 0.f, a1 = 0.f, a2 = 0.f, a3 = 0.f;
#pragma unroll
    for (int k4 = 0; k4 < 16; k4++) {
        float4 xk = reinterpret_cast<const float4*>(xr)[k4];
#pragma unroll
        for (int kk = 0; kk < 4; kk++) {
            float xv = (&xk.x)[kk];
            float4 wv = W4[(k4 * 4 + kk) * 8 + w];
            a0 = fmaf(xv, wv.x, a0);
            a1 = fmaf(xv, wv.y, a1);
            a2 = fmaf(xv, wv.z, a2);
            a3 = fmaf(xv, wv.w, a3);
        }
    }
    float dn = dsh[l];
    float4 o; o.x = dn * a0; o.y = dn * a1; o.z = dn * a2; o.w = dn * a3;
    // row = 32 halves = 8 uint2; thread w owns cols w*4..w*4+3 = uint2 index w
    reinterpret_cast<uint2*>(hout)[(size_t)(n0 + l) * 8 + w] = f4_to_h4(o);
}

// ---------------- layer-1 agg + layer-2 GEMM (HD=32 -> DN=64) --------------
// Gather: GRP=4 threads/node (uint4 each), 64 nodes/block (tail-guarded).
// Compute: 8 warps; node = (w>=4?32:0)+lane, cols = (w&3)*16..+15.
__global__ void k_agg_gemm2(const __half* __restrict__ hin,
                            __half* __restrict__ hout,
                            const float* __restrict__ bprev,
                            const float* __restrict__ W) {
    __shared__ float Ws[32 * 64];                 // 8KB
    __shared__ float xsh[64 * 36];                // 64 z-rows, XST=36
    __shared__ float dsh[64];

    for (int i = threadIdx.x; i < 32 * 64; i += blockDim.x) Ws[i] = W[i];

    const int n  = blockIdx.x * 64 + (threadIdx.x >> 2);
    const int g  = threadIdx.x & 3;
    const int nw = threadIdx.x >> 2;

    const uint4* __restrict__ h = reinterpret_cast<const uint4*>(hin);

    if (n < NN) {
        float4 A = {0.f, 0.f, 0.f, 0.f}, B = {0.f, 0.f, 0.f, 0.f};
        acc_h8(h[(size_t)n * 4 + g], A, B);       // self term
        gather16<4>(h, g_rowptr[n], g_rowptr[n + 1], g, A, B);

        const float dn = g_dinv[n];
        const float4 bpa = reinterpret_cast<const float4*>(bprev)[g * 2];
        const float4 bpb = reinterpret_cast<const float4*>(bprev)[g * 2 + 1];
        float4 za, zb;
        za.x = fmaxf(fmaf(dn, A.x, bpa.x), 0.0f);
        za.y = fmaxf(fmaf(dn, A.y, bpa.y), 0.0f);
        za.z = fmaxf(fmaf(dn, A.z, bpa.z), 0.0f);
        za.w = fmaxf(fmaf(dn, A.w, bpa.w), 0.0f);
        zb.x = fmaxf(fmaf(dn, B.x, bpb.x), 0.0f);
        zb.y = fmaxf(fmaf(dn, B.y, bpb.y), 0.0f);
        zb.z = fmaxf(fmaf(dn, B.z, bpb.z), 0.0f);
        zb.w = fmaxf(fmaf(dn, B.w, bpb.w), 0.0f);
        reinterpret_cast<float4*>(xsh + nw * 36)[g * 2]     = za;
        reinterpret_cast<float4*>(xsh + nw * 36)[g * 2 + 1] = zb;
        if (g == 0) dsh[nw] = dn;
    }
    __syncthreads();

    // compute: 64 nodes x 64 cols, 16 outputs/thread
    const int l  = threadIdx.x & 31;
    const int w  = threadIdx.x >> 5;              // 0..7
    const int nl = (w >= 4 ? 32 : 0) + l;         // local node 0..63
    const int cq = (w & 3) * 4;                   // col-quad base (of 16 quads)
    const float* xr = xsh + nl * 36;
    const float4* W4 = reinterpret_cast<const float4*>(Ws);

    float a[16];
#pragma unroll
    for (int j = 0; j < 16; j++) a[j] = 0.f;
#pragma unroll
    for (int k4 = 0; k4 < 8; k4++) {
        float4 xk = reinterpret_cast<const float4*>(xr)[k4];
#pragma unroll
        for (int kk = 0; kk < 4; kk++) {
            float xv = (&xk.x)[kk];
            int k = k4 * 4 + kk;
#pragma unroll
            for (int j4 = 0; j4 < 4; j4++) {
                float4 wv = W4[k * 16 + cq + j4];
                a[j4 * 4 + 0] = fmaf(xv, wv.x, a[j4 * 4 + 0]);
                a[j4 * 4 + 1] = fmaf(xv, wv.y, a[j4 * 4 + 1]);
                a[j4 * 4 + 2] = fmaf(xv, wv.z, a[j4 * 4 + 2]);
                a[j4 * 4 + 3] = fmaf(xv, wv.w, a[j4 * 4 + 3]);
            }
        }
    }
    const int n2 = blockIdx.x * 64 + nl;
    if (n2 < NN) {
        const float dn2 = dsh[nl];
        // out row = 64 halves = 8 uint4; thread owns 16 cols = 2 uint4
#pragma unroll
        for (int h8 = 0; h8 < 2; h8++) {
            float4 oa, ob;
            oa.x = dn2 * a[h8 * 8 + 0]; oa.y = dn2 * a[h8 * 8 + 1];
            oa.z = dn2 * a[h8 * 8 + 2]; oa.w = dn2 * a[h8 * 8 + 3];
            ob.x = dn2 * a[h8 * 8 + 4]; ob.y = dn2 * a[h8 * 8 + 5];
            ob.z = dn2 * a[h8 * 8 + 6]; ob.w = dn2 * a[h8 * 8 + 7];
            reinterpret_cast<uint4*>(hout)[(size_t)n2 * 8 + (w & 3) * 2 + h8] =
                f8_to_h8(oa, ob);
        }
    }
}

// ---------------- layer-2 agg + layer-3 GEMM (HD=64 -> DN=64) --------------
// Gather: GRP=8 threads/node (uint4 each), 32 nodes/block (exact).
// Compute: lane=node, warp=col-octet (8 warps x 8 cols).
__global__ void k_agg_gemm3(const __half* __restrict__ hin,
                            __half* __restrict__ hout,
                            const float* __restrict__ bprev,
                            const float* __restrict__ W) {
    __shared__ float Ws[64 * 64];                 // 16KB
    __shared__ float xsh[32 * 68];                // 32 z-rows, XST=68
    __shared__ float dsh[32];

    for (int i = threadIdx.x; i < 64 * 64; i += blockDim.x) Ws[i] = W[i];

    const int n  = blockIdx.x * 32 + (threadIdx.x >> 3);
    const int g  = threadIdx.x & 7;
    const int nw = threadIdx.x >> 3;

    const uint4* __restrict__ h = reinterpret_cast<const uint4*>(hin);

    float4 A = {0.f, 0.f, 0.f, 0.f}, B = {0.f, 0.f, 0.f, 0.f};
    acc_h8(h[(size_t)n * 8 + g], A, B);           // self term
    gather16<8>(h, g_rowptr[n], g_rowptr[n + 1], g, A, B);

    const float dn = g_dinv[n];
    const float4 bpa = reinterpret_cast<const float4*>(bprev)[g * 2];
    const float4 bpb = reinterpret_cast<const float4*>(bprev)[g * 2 + 1];
    float4 za, zb;
    za.x = fmaxf(fmaf(dn, A.x, bpa.x), 0.0f);
    za.y = fmaxf(fmaf(dn, A.y, bpa.y), 0.0f);
    za.z = fmaxf(fmaf(dn, A.z, bpa.z), 0.0f);
    za.w = fmaxf(fmaf(dn, A.w, bpa.w), 0.0f);
    zb.x = fmaxf(fmaf(dn, B.x, bpb.x), 0.0f);
    zb.y = fmaxf(fmaf(dn, B.y, bpb.y), 0.0f);
    zb.z = fmaxf(fmaf(dn, B.z, bpb.z), 0.0f);
    zb.w = fmaxf(fmaf(dn, B.w, bpb.w), 0.0f);
    reinterpret_cast<float4*>(xsh + nw * 68)[g * 2]     = za;
    reinterpret_cast<float4*>(xsh + nw * 68)[g * 2 + 1] = zb;
    if (g == 0) dsh[nw] = dn;
    __syncthreads();

    // compute: node = lane, cols = warp*8 .. warp*8+7
    const int l = threadIdx.x & 31;
    const int w = threadIdx.x >> 5;
    const float* xr = xsh + l * 68;
    const float4* W4 = reinterpret_cast<const float4*>(Ws);

    float a[8];
#pragma unroll
    for (int j = 0; j < 8; j++) a[j] = 0.f;
#pragma unroll
    for (int k4 = 0; k4 < 16; k4++) {
        float4 xk = reinterpret_cast<const float4*>(xr)[k4];
#pragma unroll
        for (int kk = 0; kk < 4; kk++) {
            float xv = (&xk.x)[kk];
            int k = k4 * 4 + kk;
            float4 w0 = W4[k * 16 + w * 2];
            float4 w1 = W4[k * 16 + w * 2 + 1];
            a[0] = fmaf(xv, w0.x, a[0]); a[1] = fmaf(xv, w0.y, a[1]);
            a[2] = fmaf(xv, w0.z, a[2]); a[3] = fmaf(xv, w0.w, a[3]);
            a[4] = fmaf(xv, w1.x, a[4]); a[5] = fmaf(xv, w1.y, a[5]);
            a[6] = fmaf(xv, w1.z, a[6]); a[7] = fmaf(xv, w1.w, a[7]);
        }
    }
    const float dn2 = dsh[l];
    const int n2 = blockIdx.x * 32 + l;
    float4 oa, ob;
    oa.x = dn2 * a[0]; oa.y = dn2 * a[1]; oa.z = dn2 * a[2]; oa.w = dn2 * a[3];
    ob.x = dn2 * a[4]; ob.y = dn2 * a[5]; ob.z = dn2 * a[6]; ob.w = dn2 * a[7];
    // out row = 64 halves = 8 uint4; thread owns cols w*8..w*8+7 = uint4 index w
    reinterpret_cast<uint4*>(hout)[(size_t)n2 * 8 + w] = f8_to_h8(oa, ob);
}

// ---------------- fused aggregate + bias + row L2-normalize (fp32 out) -----
// Gather: GRP=8 threads/node (uint4 each), 32 nodes/block.
__global__ void k_agg_final(const __half* __restrict__ hin,
                            const float* __restrict__ b3,
                            float* __restrict__ out) {
    const int n = blockIdx.x * 32 + (threadIdx.x >> 3);
    const int g = threadIdx.x & 7;

    const uint4* __restrict__ h = reinterpret_cast<const uint4*>(hin);

    float4 A = {0.f, 0.f, 0.f, 0.f}, B = {0.f, 0.f, 0.f, 0.f};
    acc_h8(h[(size_t)n * 8 + g], A, B);
    gather16<8>(h, g_rowptr[n], g_rowptr[n + 1], g, A, B);

    const float dn = g_dinv[n];
    const float4 bpa = reinterpret_cast<const float4*>(b3)[g * 2];
    const float4 bpb = reinterpret_cast<const float4*>(b3)[g * 2 + 1];
    float4 va, vb;
    va.x = fmaf(dn, A.x, bpa.x); va.y = fmaf(dn, A.y, bpa.y);
    va.z = fmaf(dn, A.z, bpa.z); va.w = fmaf(dn, A.w, bpa.w);
    vb.x = fmaf(dn, B.x, bpb.x); vb.y = fmaf(dn, B.y, bpb.y);
    vb.z = fmaf(dn, B.z, bpb.z); vb.w = fmaf(dn, B.w, bpb.w);

    float s = va.x * va.x + va.y * va.y + va.z * va.z + va.w * va.w
            + vb.x * vb.x + vb.y * vb.y + vb.z * vb.z + vb.w * vb.w;
    // 8-lane group reduction (offsets < 8 stay within the node's group)
    s += __shfl_xor_sync(0xffffffffu, s, 1);
    s += __shfl_xor_sync(0xffffffffu, s, 2);
    s += __shfl_xor_sync(0xffffffffu, s, 4);
    float inv = 1.0f / fmaxf(sqrtf(s), 1e-12f);

    float4 oa, ob;
    oa.x = va.x * inv; oa.y = va.y * inv; oa.z = va.z * inv; oa.w = va.w * inv;
    ob.x = vb.x * inv; ob.y = vb.y * inv; ob.z = vb.z * inv; ob.w = vb.w * inv;
    // out row = 64 fp32 = 16 float4; thread owns cols g*8..g*8+7
    reinterpret_cast<float4*>(out)[(size_t)n * 16 + g * 2]     = oa;
    reinterpret_cast<float4*>(out)[(size_t)n * 16 + g * 2 + 1] = ob;
}

// ---------------- launch ----------------
extern "C" void kernel_launch(void* const* d_in, const int* in_sizes, int n_in,
                              void* d_out, int out_size) {
    const float* x  = (const float*)d_in[0];
    const int*   ei = (const int*)d_in[1];   // int32 (JAX x64 off) or int64 via probe
    const float* W1 = (const float*)d_in[2];
    const float* b1 = (const float*)d_in[3];
    const float* W2 = (const float*)d_in[4];
    const float* b2 = (const float*)d_in[5];
    const float* W3 = (const float*)d_in[6];
    const float* b3 = (const float*)d_in[7];
    float* out = (float*)d_out;

    __half *hA, *hB;
    cudaGetSymbolAddress((void**)&hA, g_hA);
    cudaGetSymbolAddress((void**)&hB, g_hB);
    int* cnt;
    cudaGetSymbolAddress((void**)&cnt, g_cnt);

    const int TB = 256;
    const int EDGE2_BLKS = (NE / 2 + TB - 1) / TB;   // 2344 (2 edges/thread)
    const int G1_BLKS    = NN / 32;                  // 3125 (32 nodes/block)

    // CSR + dinv (shared by all 3 layers)
    cudaMemsetAsync(cnt, 0, NN * sizeof(int));
    k_edges<<<EDGE2_BLKS, TB>>>(ei);
    k_scanA<<<NBLK, SCAN_B>>>();
    k_scanC<<<NBLK, SCAN_B>>>();

    // CSR fill + Layer-1 GEMM (independent, one kernel)
    k_fill_gemm1<<<EDGE2_BLKS + G1_BLKS, TB>>>(ei, EDGE2_BLKS, x, W1, hA);

    // Layer 1 aggregate + Layer 2 GEMM: hB = dinv * (relu(agg(hA)+b1) @ W2)
    k_agg_gemm2<<<(NN + 63) / 64, TB>>>(hA, hB, b1, W2);   // 1563 blocks
    // Layer 2 aggregate + Layer 3 GEMM: hA = dinv * (relu(agg(hB)+b2) @ W3)
    k_agg_gemm3<<<NN / 32, TB>>>(hB, hA, b2, W3);          // 3125 blocks
    // Layer 3 aggregate + b3 + row L2-normalize -> out
    k_agg_final<<<NN / 32, TB>>>(hA, b3, out);             // 3125 blocks
}